// round 15
// baseline (speedup 1.0000x reference)
#include <cuda_runtime.h>
#include <cuda_fp16.h>
#include <cstdint>

#define NN 4096
#define FIN 512
#define FO 64
#define NH 8
#define ALPHA 0.2f
#define OUTW (NH * FO)  /* 512 */
#define LOG2E 1.4426950408889634f
#define NWORD (NN / 32)  /* 128 */

// ---------------------------------------------------------------------------
// Scratch (static device globals)
// ---------------------------------------------------------------------------
__device__ unsigned short g_h16hi[NN * FIN];     // fp16 hi of h, [n][k]
__device__ unsigned short g_h16lo[NN * FIN];     // fp16 lo of h, [n][k]
__device__ unsigned short g_w16hi[NH * FIN * FO];// fp16 hi of W, [h][k][n]
__device__ unsigned short g_w16lo[NH * FIN * FO];
__device__ unsigned short g_wh16[NH * NN * FO];  // fp16 Wh, [h][n][o]
__device__ float g_el[NH * NN];                  // el * log2e (incl bA)
__device__ float g_er[NH * NN];                  // er * log2e
__device__ unsigned int g_ermax_enc[NH];         // order-preserving encoded max
__device__ uint32_t g_bits[NN * NWORD];          // mask bitmap [i][j/32]

__device__ __forceinline__ uint32_t smem_u32(const void* p) {
    uint32_t a;
    asm("{ .reg .u64 t; cvta.to.shared.u64 t, %1; cvt.u32.u64 %0, t; }" : "=r"(a) : "l"(p));
    return a;
}

__device__ __forceinline__ unsigned int f2ord(float f) {
    unsigned int u = __float_as_uint(f);
    return (u & 0x80000000u) ? ~u : (u | 0x80000000u);
}
__device__ __forceinline__ float ord2f(unsigned int k) {
    unsigned int u = (k & 0x80000000u) ? (k & 0x7FFFFFFFu) : ~k;
    return __uint_as_float(u);
}

#define MMA16816F16(acc, a0, a1, a2, a3, b0, b1) \
    asm volatile("mma.sync.aligned.m16n8k16.row.col.f32.f16.f16.f32 " \
        "{%0,%1,%2,%3}, {%4,%5,%6,%7}, {%8,%9}, {%0,%1,%2,%3};" \
        : "+f"((acc)[0]), "+f"((acc)[1]), "+f"((acc)[2]), "+f"((acc)[3]) \
        : "r"(a0), "r"(a1), "r"(a2), "r"(a3), "r"(b0), "r"(b1))

#define LDSM4T(r0, r1, r2, r3, a) \
    asm volatile("ldmatrix.sync.aligned.m8n8.x4.trans.shared.b16 {%0,%1,%2,%3}, [%4];" \
        : "=r"(r0), "=r"(r1), "=r"(r2), "=r"(r3) : "r"(a))

#define LDSM4(r0, r1, r2, r3, a) \
    asm volatile("ldmatrix.sync.aligned.m8n8.x4.shared.b16 {%0,%1,%2,%3}, [%4];" \
        : "=r"(r0), "=r"(r1), "=r"(r2), "=r"(r3) : "r"(a))

__device__ __forceinline__ uint32_t pack_hi_f16x2(float a, float b) {
    uint32_t r;
    asm("cvt.rn.f16x2.f32 %0, %1, %2;" : "=r"(r) : "f"(b), "f"(a));
    return r;
}

// ---------------------------------------------------------------------------
// Kernel P: convert h and W to fp16 hi/lo; init ermax. (mask scan moved into
// wh_mma where its DRAM latency hides under the MMA mainloop)
// ---------------------------------------------------------------------------
__global__ void __launch_bounds__(256) prep_kernel(
    const float* __restrict__ h, const float* __restrict__ W)
{
    if (blockIdx.x == 0 && threadIdx.x < NH)
        g_ermax_enc[threadIdx.x] = 0u;  // below every encoded float

    const int stride = gridDim.x * 256;
    for (int i = blockIdx.x * 256 + threadIdx.x; i < NN * FIN / 4; i += stride) {
        float4 v = ((const float4*)h)[i];
        __half hx = __float2half_rn(v.x), hy = __float2half_rn(v.y);
        __half hz = __float2half_rn(v.z), hw = __float2half_rn(v.w);
        uint32_t hi0 = (uint32_t)__half_as_ushort(hx) | ((uint32_t)__half_as_ushort(hy) << 16);
        uint32_t hi1 = (uint32_t)__half_as_ushort(hz) | ((uint32_t)__half_as_ushort(hw) << 16);
        uint32_t lo0 = pack_hi_f16x2(v.x - __half2float(hx), v.y - __half2float(hy));
        uint32_t lo1 = pack_hi_f16x2(v.z - __half2float(hz), v.w - __half2float(hw));
        ((uint2*)g_h16hi)[i] = make_uint2(hi0, hi1);
        ((uint2*)g_h16lo)[i] = make_uint2(lo0, lo1);
    }
    for (int i = blockIdx.x * 256 + threadIdx.x; i < NH * FIN * FO / 4; i += stride) {
        float4 v = ((const float4*)W)[i];
        __half hx = __float2half_rn(v.x), hy = __float2half_rn(v.y);
        __half hz = __float2half_rn(v.z), hw = __float2half_rn(v.w);
        uint32_t hi0 = (uint32_t)__half_as_ushort(hx) | ((uint32_t)__half_as_ushort(hy) << 16);
        uint32_t hi1 = (uint32_t)__half_as_ushort(hz) | ((uint32_t)__half_as_ushort(hw) << 16);
        uint32_t lo0 = pack_hi_f16x2(v.x - __half2float(hx), v.y - __half2float(hy));
        uint32_t lo1 = pack_hi_f16x2(v.z - __half2float(hz), v.w - __half2float(hw));
        ((uint2*)g_w16hi)[i] = make_uint2(hi0, hi1);
        ((uint2*)g_w16lo)[i] = make_uint2(lo0, lo1);
    }
}

// ---------------------------------------------------------------------------
// Kernel A: Wh = h @ W + bW via fp16 HMMA hi/lo split; mask->bits scan fused
// into the mainloop shadow (loads issued at chunk start, ballots consumed
// between kt pairs); fused el/er + per-head er-max.
// ---------------------------------------------------------------------------
#define ASTRIDE 72
#define WH_SMEM (128 * ASTRIDE * 2 * 2 + 64 * ASTRIDE * 2 * 2)

__global__ void __launch_bounds__(256) wh_mma_kernel(
    const float* __restrict__ bW, const float* __restrict__ a_l,
    const float* __restrict__ a_r, const float* __restrict__ bA,
    const int* __restrict__ mask)
{
    extern __shared__ __align__(16) unsigned short sm[];
    unsigned short* Ah = sm;
    unsigned short* Al = Ah + 128 * ASTRIDE;
    unsigned short* Bh = Al + 128 * ASTRIDE;
    unsigned short* Bl = Bh + 64 * ASTRIDE;
    __shared__ float redmax[8];

    const int t    = threadIdx.x;
    const int warp = t >> 5;
    const int lane = t & 31;
    const int i0   = blockIdx.x * 128;
    const int hh   = blockIdx.y;
    const int cta  = blockIdx.y * (NN / 128) + blockIdx.x;  // 0..255

    const uint32_t ahB = smem_u32(Ah), alB = smem_u32(Al);
    const uint32_t bhB = smem_u32(Bh), blB = smem_u32(Bl);

    float acc[8][4];
#pragma unroll
    for (int n = 0; n < 8; n++)
#pragma unroll
        for (int j = 0; j < 4; j++) acc[n][j] = 0.f;

    const uint32_t aRow = (uint32_t)(16 * warp + (lane & 15)) * (ASTRIDE * 2) + ((lane & 16) ? 16 : 0);
    const uint32_t bRow = (uint32_t)(lane & 15) * (ASTRIDE * 2) + ((lane & 16) ? 16 : 0);

    // mask-scan work assignment: 16-word groups, 16 per warp, 2 per chunk
    const int gBase = (cta * 8 + warp) * 16;

    // helper macros expressed as lambdas
    auto mload = [&](int G, int* m) {
        int w0 = 16 * G;
        int row = w0 >> 7;
        int wd  = w0 & (NWORD - 1);
        const int* base = mask + (size_t)row * NN + wd * 32 + lane;
#pragma unroll
        for (int k = 0; k < 16; k++) m[k] = base[32 * k];
    };
    auto mstore = [&](int G, const int* m) {
        uint32_t b[16];
#pragma unroll
        for (int k = 0; k < 16; k++) b[k] = __ballot_sync(0xffffffffu, m[k] > 0);
        if (lane == 0) {
            int w0 = 16 * G;
#pragma unroll
            for (int s = 0; s < 4; s++)
                *(uint4*)(g_bits + w0 + 4 * s) =
                    make_uint4(b[4 * s], b[4 * s + 1], b[4 * s + 2], b[4 * s + 3]);
        }
    };

    for (int ch = 0; ch < FIN / 64; ch++) {
        const int kc = ch * 64;
        __syncthreads();
#pragma unroll
        for (int it = 0; it < 4; it++) {
            int id = t + 256 * it;
            int r = id >> 3, c = id & 7;
            size_t src = (size_t)(i0 + r) * FIN + kc + c * 8;
            *(uint4*)&Ah[r * ASTRIDE + c * 8] = *(const uint4*)(g_h16hi + src);
            *(uint4*)&Al[r * ASTRIDE + c * 8] = *(const uint4*)(g_h16lo + src);
        }
#pragma unroll
        for (int it = 0; it < 2; it++) {
            int id = t + 256 * it;
            int r = id >> 3, c = id & 7;
            size_t src = ((size_t)hh * FIN + kc + r) * FO + c * 8;
            *(uint4*)&Bh[r * ASTRIDE + c * 8] = *(const uint4*)(g_w16hi + src);
            *(uint4*)&Bl[r * ASTRIDE + c * 8] = *(const uint4*)(g_w16lo + src);
        }

        // issue mask group 0 loads (latency hides under kt 0..1 MMAs)
        const int G0 = gBase + ch * 2;
        int mA[16];
        mload(G0, mA);

        __syncthreads();

#pragma unroll
        for (int half = 0; half < 2; half++) {
#pragma unroll
            for (int ki = 0; ki < 2; ki++) {
                const int kt = half * 2 + ki;
                uint32_t ah0, ah1, ah2, ah3, al0, al1, al2, al3;
                LDSM4(ah0, ah1, ah2, ah3, ahB + aRow + kt * 32);
                LDSM4(al0, al1, al2, al3, alB + aRow + kt * 32);
                const uint32_t kOff = (uint32_t)(16 * kt) * (ASTRIDE * 2) + bRow;

                uint32_t bhc[4], blc[4], bhn[4], bln[4];
                LDSM4T(bhc[0], bhc[1], bhc[2], bhc[3], bhB + kOff);
                LDSM4T(blc[0], blc[1], blc[2], blc[3], blB + kOff);
#pragma unroll
                for (int ntp = 0; ntp < 4; ntp++) {
                    if (ntp < 3) {
                        LDSM4T(bhn[0], bhn[1], bhn[2], bhn[3], bhB + kOff + 32 * (ntp + 1));
                        LDSM4T(bln[0], bln[1], bln[2], bln[3], blB + kOff + 32 * (ntp + 1));
                    }
                    MMA16816F16(acc[2 * ntp],     ah0, ah1, ah2, ah3, bhc[0], bhc[1]);
                    MMA16816F16(acc[2 * ntp],     al0, al1, al2, al3, bhc[0], bhc[1]);
                    MMA16816F16(acc[2 * ntp],     ah0, ah1, ah2, ah3, blc[0], blc[1]);
                    MMA16816F16(acc[2 * ntp + 1], ah0, ah1, ah2, ah3, bhc[2], bhc[3]);
                    MMA16816F16(acc[2 * ntp + 1], al0, al1, al2, al3, bhc[2], bhc[3]);
                    MMA16816F16(acc[2 * ntp + 1], ah0, ah1, ah2, ah3, blc[2], blc[3]);
                    if (ntp < 3) {
#pragma unroll
                        for (int z = 0; z < 4; z++) { bhc[z] = bhn[z]; blc[z] = bln[z]; }
                    }
                }
            }
            // consume current mask group; issue next
            if (half == 0) {
                mstore(G0, mA);
                mload(G0 + 1, mA);
            } else {
                mstore(G0 + 1, mA);
            }
        }
    }

    // ---- epilogue: bias, store fp16 Wh, fused el/er, er-max ----
    const int q  = lane >> 2;
    const int c2 = 2 * (lane & 3);
    const int r0 = i0 + 16 * warp + q;
    const int r1 = r0 + 8;

    float dl0 = 0.f, dr0 = 0.f, dl1 = 0.f, dr1 = 0.f;
#pragma unroll
    for (int nt = 0; nt < 8; nt++) {
        int col = 8 * nt + c2;
        float2 bw = *(const float2*)(bW + hh * FO + col);
        float2 al = *(const float2*)(a_l + hh * FO + col);
        float2 ar = *(const float2*)(a_r + hh * FO + col);
        float v00 = acc[nt][0] + bw.x, v01 = acc[nt][1] + bw.y;
        float v10 = acc[nt][2] + bw.x, v11 = acc[nt][3] + bw.y;
        *(uint32_t*)(g_wh16 + ((size_t)hh * NN + r0) * FO + col) = pack_hi_f16x2(v00, v01);
        *(uint32_t*)(g_wh16 + ((size_t)hh * NN + r1) * FO + col) = pack_hi_f16x2(v10, v11);
        dl0 += v00 * al.x + v01 * al.y;
        dr0 += v00 * ar.x + v01 * ar.y;
        dl1 += v10 * al.x + v11 * al.y;
        dr1 += v10 * ar.x + v11 * ar.y;
    }
#pragma unroll
    for (int off = 1; off < 4; off <<= 1) {
        dl0 += __shfl_xor_sync(0xffffffffu, dl0, off);
        dr0 += __shfl_xor_sync(0xffffffffu, dr0, off);
        dl1 += __shfl_xor_sync(0xffffffffu, dl1, off);
        dr1 += __shfl_xor_sync(0xffffffffu, dr1, off);
    }
    float er0s = dr0 * LOG2E, er1s = dr1 * LOG2E;
    if ((lane & 3) == 0) {
        float ba = bA[hh];
        g_el[hh * NN + r0] = (dl0 + ba) * LOG2E;
        g_er[hh * NN + r0] = er0s;
        g_el[hh * NN + r1] = (dl1 + ba) * LOG2E;
        g_er[hh * NN + r1] = er1s;
    }
    float wm = fmaxf(er0s, er1s);
#pragma unroll
    for (int off = 4; off < 32; off <<= 1)
        wm = fmaxf(wm, __shfl_xor_sync(0xffffffffu, wm, off));
    if (lane == 0) redmax[warp] = wm;
    __syncthreads();
    if (t == 0) {
        float m = redmax[0];
#pragma unroll
        for (int w = 1; w < 8; w++) m = fmaxf(m, redmax[w]);
        atomicMax(&g_ermax_enc[hh], f2ord(m));
    }
}

// ---------------------------------------------------------------------------
// Kernel C: fp16 HMMA flash-GAT, 128-wide j tiles; scores SW-pipelined one kt
// ahead; f16x2 fused score math. (unchanged from R14 best)
// ---------------------------------------------------------------------------
__device__ __forceinline__ float elu(float v) {
    return v > 0.f ? v : (__expf(v) - 1.f);
}

#define ALPHA2_F16 0x32663266u  /* (0.2, 0.2) fp16x2 */

__device__ __forceinline__ uint32_t pscore2(float elp, uint32_t d2, float2 er, uint32_t b2) {
    float x0 = elp + er.x;
    float x1 = elp + er.y;
    uint32_t xh, yh, mh, pe;
    asm("cvt.rn.f16x2.f32 %0, %1, %2;" : "=r"(xh) : "f"(x1), "f"(x0));
    asm("fma.rn.f16x2 %0, %1, %2, %3;" : "=r"(yh) : "r"(ALPHA2_F16), "r"(xh), "r"(d2));
    asm("max.f16x2 %0, %1, %2;" : "=r"(mh) : "r"(xh), "r"(yh));
    asm("ex2.approx.f16x2 %0, %1;" : "=r"(pe) : "r"(mh));
    uint32_t msk = ((b2 & 1u) ? 0x0000FFFFu : 0u) | ((b2 & 2u) ? 0xFFFF0000u : 0u);
    return pe & msk;
}

#define BSTRIDE 72
#define JT 128
#define ATTN_BS_BYTES (2 * JT * BSTRIDE * 2)            /* 36864 */
#define ATTN_SMEM (ATTN_BS_BYTES + 1024 + NN * 4)       /* 54272 */

__global__ void __launch_bounds__(256, 2) gat_attn_mma_kernel(float* __restrict__ out)
{
    extern __shared__ __align__(16) char dsm[];
    unsigned short* Bs = (unsigned short*)dsm;
    float2* els2 = (float2*)(dsm + ATTN_BS_BYTES);
    float* ers = (float*)(dsm + ATTN_BS_BYTES + 1024);

    const int t    = threadIdx.x;
    const int warp = t >> 5;
    const int lane = t & 31;
    const int i0   = blockIdx.x * 128;
    const int hh   = blockIdx.y;

    {
        const float4* src = (const float4*)(g_er + hh * NN);
#pragma unroll
        for (int it = 0; it < NN / 4 / 256; it++)
            ((float4*)ers)[t + 256 * it] = src[t + 256 * it];
    }

    if (t < 128) {
        float e = g_el[hh * NN + i0 + t];
        float z = e + ord2f(g_ermax_enc[hh]);
        float c = fmaxf(z, ALPHA * z);
        float d = (ALPHA - 1.f) * c;
        __half hd = __float2half_rn(d);
        uint32_t d2 = (uint32_t)__half_as_ushort(hd);
        d2 |= d2 << 16;
        els2[t] = make_float2(e - c, __uint_as_float(d2));
    }

    const int q  = lane >> 2;
    const int c2 = 2 * (lane & 3);
    const int rw0 = 16 * warp + q;

    const unsigned short* gwh = g_wh16 + (size_t)hh * NN * FO;
    const uint32_t* bitbase =
        g_bits + (size_t)(i0 + 16 * warp + (lane >> 1)) * NWORD + (lane & 1) * 2;

    const uint32_t bBase = smem_u32(Bs);
    const uint32_t lrowOff = (uint32_t)(lane & 15) * (BSTRIDE * 2) + ((lane & 16) ? 16 : 0);

    const int lk0 = t >> 3, lc0 = t & 7;
    const int lk1 = (t + 256) >> 3, lc1 = t & 7;

    float acc[8][4];
#pragma unroll
    for (int n = 0; n < 8; n++)
#pragma unroll
        for (int j = 0; j < 4; j++) acc[n][j] = 0.f;
    float accd[4] = {0.f, 0.f, 0.f, 0.f};
    const uint32_t ONES = 0x3C003C00u;

    {
#pragma unroll
        for (int hf = 0; hf < 2; hf++) {
            uint4 va = *(const uint4*)(gwh + (size_t)(hf * 64 + lk0) * FO + lc0 * 8);
            uint4 vb = *(const uint4*)(gwh + (size_t)(hf * 64 + lk1) * FO + lc1 * 8);
            *(uint4*)&Bs[(hf * 64 + lk0) * BSTRIDE + lc0 * 8] = va;
            *(uint4*)&Bs[(hf * 64 + lk1) * BSTRIDE + lc1 * 8] = vb;
        }
    }
    uint2 bvNext = *(const uint2*)(bitbase);
    __syncthreads();

    const float2 ec0 = els2[rw0];
    const float2 ec1 = els2[rw0 + 8];
    const float elp0 = ec0.x, elp1 = ec1.x;
    const uint32_t d20 = __float_as_uint(ec0.y), d21 = __float_as_uint(ec1.y);

    uint32_t w0[4], w1[4];
    auto distrib = [&](uint2 bv) {
        w0[0] = __shfl_sync(0xffffffffu, bv.x, 2 * q);
        w0[1] = __shfl_sync(0xffffffffu, bv.y, 2 * q);
        w0[2] = __shfl_sync(0xffffffffu, bv.x, 2 * q + 1);
        w0[3] = __shfl_sync(0xffffffffu, bv.y, 2 * q + 1);
        w1[0] = __shfl_sync(0xffffffffu, bv.x, 2 * q + 16);
        w1[1] = __shfl_sync(0xffffffffu, bv.y, 2 * q + 16);
        w1[2] = __shfl_sync(0xffffffffu, bv.x, 2 * q + 17);
        w1[3] = __shfl_sync(0xffffffffu, bv.y, 2 * q + 17);
    };

    auto scoreblk = [&](int jb0, int kt, uint32_t* a) {
        const int jb = jb0 + 16 * kt + c2;
        float2 e0 = *(const float2*)(ers + jb);
        float2 e1 = *(const float2*)(ers + jb + 8);
        const int wi = kt >> 1;
        const int sb = (kt & 1) * 16;
        uint32_t v0 = w0[wi] >> (sb + c2);
        uint32_t v1 = w1[wi] >> (sb + c2);
        a[0] = pscore2(elp0, d20, e0, v0 & 3u);
        a[1] = pscore2(elp1, d21, e0, v1 & 3u);
        a[2] = pscore2(elp0, d20, e1, (v0 >> 8) & 3u);
        a[3] = pscore2(elp1, d21, e1, (v1 >> 8) & 3u);
    };

    distrib(bvNext);
    uint32_t aF[4];
    scoreblk(0, 0, aF);

    for (int tile = 0; tile < NN / JT; tile++) {
        const int j0 = tile * JT;
        const int cur = tile & 1;
        const bool last = (tile == NN / JT - 1);

        if (!last) bvNext = *(const uint2*)(bitbase + (tile + 1) * 4);

        uint4 na, nb;
        if (!last) {
            const unsigned short* src = gwh + (size_t)(j0 + JT) * FO;
            na = *(const uint4*)(src + (size_t)lk0 * FO + lc0 * 8);
            nb = *(const uint4*)(src + (size_t)lk1 * FO + lc1 * 8);
        }

        const uint32_t bufOff = bBase + cur * (JT * BSTRIDE * 2) + lrowOff;
        unsigned short* dst = &Bs[(cur ^ 1) * JT * BSTRIDE];

#pragma unroll
        for (int kt = 0; kt < 8; kt++) {
            uint32_t aN[4];
            if (kt < 7)
                scoreblk(j0, kt + 1, aN);

            const uint32_t kOff = bufOff + (uint32_t)(16 * kt) * (BSTRIDE * 2);

            uint32_t bc[4], bn[4];
            LDSM4T(bc[0], bc[1], bc[2], bc[3], kOff);
#pragma unroll
            for (int ntp = 0; ntp < 4; ntp++) {
                if (ntp < 3)
                    LDSM4T(bn[0], bn[1], bn[2], bn[3], kOff + 32 * (ntp + 1));
                MMA16816F16(acc[2 * ntp],     aF[0], aF[1], aF[2], aF[3], bc[0], bc[1]);
                MMA16816F16(acc[2 * ntp + 1], aF[0], aF[1], aF[2], aF[3], bc[2], bc[3]);
                if (ntp < 3) {
#pragma unroll
                    for (int z = 0; z < 4; z++) bc[z] = bn[z];
                }
            }
            MMA16816F16(accd, aF[0], aF[1], aF[2], aF[3], ONES, ONES);

            if (kt == 3 && !last) {
                *(uint4*)&dst[lk0 * BSTRIDE + lc0 * 8] = na;
                *(uint4*)&dst[lk1 * BSTRIDE + lc1 * 8] = nb;
                const unsigned short* src = gwh + (size_t)(j0 + JT + 64) * FO;
                na = *(const uint4*)(src + (size_t)lk0 * FO + lc0 * 8);
                nb = *(const uint4*)(src + (size_t)lk1 * FO + lc1 * 8);
            }

            if (kt < 7) {
                aF[0] = aN[0]; aF[1] = aN[1]; aF[2] = aN[2]; aF[3] = aN[3];
            }
        }

        if (!last) {
            *(uint4*)&dst[(64 + lk0) * BSTRIDE + lc0 * 8] = na;
            *(uint4*)&dst[(64 + lk1) * BSTRIDE + lc1 * 8] = nb;
            distrib(bvNext);
            scoreblk(j0 + JT, 0, aF);
        }
        __syncthreads();
    }

    const float inv0 = 1.f / accd[0];
    const float inv1 = 1.f / accd[2];

    float* ob0 = out + (size_t)(i0 + rw0) * OUTW + hh * FO + c2;
    float* ob1 = ob0 + (size_t)8 * OUTW;
#pragma unroll
    for (int nt = 0; nt < 8; nt++) {
        float2 v0 = make_float2(elu(acc[nt][0] * inv0), elu(acc[nt][1] * inv0));
        float2 v1 = make_float2(elu(acc[nt][2] * inv1), elu(acc[nt][3] * inv1));
        *(float2*)(ob0 + 8 * nt) = v0;
        *(float2*)(ob1 + 8 * nt) = v1;
    }
}

// ---------------------------------------------------------------------------
extern "C" void kernel_launch(void* const* d_in, const int* in_sizes, int n_in,
                              void* d_out, int out_size)
{
    const float* h    = (const float*)d_in[0];  // [N, FIN]
    const int*   mask = (const int*)  d_in[1];  // [N, N]
    const float* W    = (const float*)d_in[2];  // [H, FIN, FO]
    const float* bW   = (const float*)d_in[3];  // [H, FO]
    const float* a_l  = (const float*)d_in[4];  // [H, FO]
    const float* a_r  = (const float*)d_in[5];  // [H, FO]
    const float* bA   = (const float*)d_in[6];  // [H]
    float* out = (float*)d_out;                 // [N, H*FO]

    cudaFuncSetAttribute(wh_mma_kernel,
                         cudaFuncAttributeMaxDynamicSharedMemorySize, WH_SMEM);
    cudaFuncSetAttribute(gat_attn_mma_kernel,
                         cudaFuncAttributeMaxDynamicSharedMemorySize, ATTN_SMEM);

    prep_kernel<<<1024, 256>>>(h, W);
    wh_mma_kernel<<<dim3(NN / 128, NH), 256, WH_SMEM>>>(bW, a_l, a_r, bA, mask);
    gat_attn_mma_kernel<<<dim3(NN / 128, NH), 256, ATTN_SMEM>>>(out);
}

// round 16
// speedup vs baseline: 1.1198x; 1.1198x over previous
#include <cuda_runtime.h>
#include <cuda_fp16.h>
#include <cstdint>

#define NN 4096
#define FIN 512
#define FO 64
#define NH 8
#define ALPHA 0.2f
#define OUTW (NH * FO)  /* 512 */
#define LOG2E 1.4426950408889634f
#define NWORD (NN / 32)  /* 128 */

// ---------------------------------------------------------------------------
// Scratch (static device globals)
// ---------------------------------------------------------------------------
__device__ unsigned short g_h16hi[NN * FIN];     // fp16 hi of h, [n][k]
__device__ unsigned short g_h16lo[NN * FIN];     // fp16 lo of h, [n][k]
__device__ unsigned short g_w16hi[NH * FIN * FO];// fp16 hi of W, [h][k][n]
__device__ unsigned short g_w16lo[NH * FIN * FO];
__device__ unsigned short g_wh16[NH * NN * FO];  // fp16 Wh, [h][n][o]
__device__ float g_el[NH * NN];                  // el * log2e (incl bA)
__device__ float g_er[NH * NN];                  // er * log2e
__device__ unsigned int g_ermax_enc[NH];         // order-preserving encoded max
__device__ uint32_t g_bits[NN * NWORD];          // mask bitmap [i][j/32]

__device__ __forceinline__ uint32_t smem_u32(const void* p) {
    uint32_t a;
    asm("{ .reg .u64 t; cvta.to.shared.u64 t, %1; cvt.u32.u64 %0, t; }" : "=r"(a) : "l"(p));
    return a;
}

__device__ __forceinline__ unsigned int f2ord(float f) {
    unsigned int u = __float_as_uint(f);
    return (u & 0x80000000u) ? ~u : (u | 0x80000000u);
}
__device__ __forceinline__ float ord2f(unsigned int k) {
    unsigned int u = (k & 0x80000000u) ? (k & 0x7FFFFFFFu) : ~k;
    return __uint_as_float(u);
}

#define MMA16816F16(acc, a0, a1, a2, a3, b0, b1) \
    asm volatile("mma.sync.aligned.m16n8k16.row.col.f32.f16.f16.f32 " \
        "{%0,%1,%2,%3}, {%4,%5,%6,%7}, {%8,%9}, {%0,%1,%2,%3};" \
        : "+f"((acc)[0]), "+f"((acc)[1]), "+f"((acc)[2]), "+f"((acc)[3]) \
        : "r"(a0), "r"(a1), "r"(a2), "r"(a3), "r"(b0), "r"(b1))

#define LDSM4T(r0, r1, r2, r3, a) \
    asm volatile("ldmatrix.sync.aligned.m8n8.x4.trans.shared.b16 {%0,%1,%2,%3}, [%4];" \
        : "=r"(r0), "=r"(r1), "=r"(r2), "=r"(r3) : "r"(a))

#define LDSM4(r0, r1, r2, r3, a) \
    asm volatile("ldmatrix.sync.aligned.m8n8.x4.shared.b16 {%0,%1,%2,%3}, [%4];" \
        : "=r"(r0), "=r"(r1), "=r"(r2), "=r"(r3) : "r"(a))

__device__ __forceinline__ uint32_t pack_hi_f16x2(float a, float b) {
    uint32_t r;
    asm("cvt.rn.f16x2.f32 %0, %1, %2;" : "=r"(r) : "f"(b), "f"(a));
    return r;
}

// ---------------------------------------------------------------------------
// Kernel P: mask -> bitmap (MLP-16, issued first: BW stream); then convert
// h and W to fp16 hi/lo; init ermax. grid 2048 for chip-wide MLP.
// ---------------------------------------------------------------------------
__global__ void __launch_bounds__(256) prep_kernel(
    const float* __restrict__ h, const float* __restrict__ W,
    const int* __restrict__ mask)
{
    if (blockIdx.x == 0 && threadIdx.x < NH)
        g_ermax_enc[threadIdx.x] = 0u;  // below every encoded float

    const int stride = gridDim.x * 256;

    // mask -> bits first: 16 words per warp-iteration (MLP=16)
    {
        const int wid_g = (blockIdx.x * 256 + threadIdx.x) >> 5;
        const int lane  = threadIdx.x & 31;
        const int nwarp = stride >> 5;
        for (int g = wid_g; g < NN * NWORD / 16; g += nwarp) {
            int w0  = 16 * g;
            int row = w0 >> 7;
            int wd  = w0 & (NWORD - 1);
            const int* base = mask + (size_t)row * NN + wd * 32 + lane;
            int m[16];
#pragma unroll
            for (int k = 0; k < 16; k++) m[k] = base[32 * k];
            uint32_t b[16];
#pragma unroll
            for (int k = 0; k < 16; k++) b[k] = __ballot_sync(0xffffffffu, m[k] > 0);
            if (lane == 0) {
#pragma unroll
                for (int s = 0; s < 4; s++)
                    *(uint4*)(g_bits + w0 + 4 * s) =
                        make_uint4(b[4 * s], b[4 * s + 1], b[4 * s + 2], b[4 * s + 3]);
            }
        }
    }

    for (int i = blockIdx.x * 256 + threadIdx.x; i < NN * FIN / 4; i += stride) {
        float4 v = ((const float4*)h)[i];
        __half hx = __float2half_rn(v.x), hy = __float2half_rn(v.y);
        __half hz = __float2half_rn(v.z), hw = __float2half_rn(v.w);
        uint32_t hi0 = (uint32_t)__half_as_ushort(hx) | ((uint32_t)__half_as_ushort(hy) << 16);
        uint32_t hi1 = (uint32_t)__half_as_ushort(hz) | ((uint32_t)__half_as_ushort(hw) << 16);
        uint32_t lo0 = pack_hi_f16x2(v.x - __half2float(hx), v.y - __half2float(hy));
        uint32_t lo1 = pack_hi_f16x2(v.z - __half2float(hz), v.w - __half2float(hw));
        ((uint2*)g_h16hi)[i] = make_uint2(hi0, hi1);
        ((uint2*)g_h16lo)[i] = make_uint2(lo0, lo1);
    }
    for (int i = blockIdx.x * 256 + threadIdx.x; i < NH * FIN * FO / 4; i += stride) {
        float4 v = ((const float4*)W)[i];
        __half hx = __float2half_rn(v.x), hy = __float2half_rn(v.y);
        __half hz = __float2half_rn(v.z), hw = __float2half_rn(v.w);
        uint32_t hi0 = (uint32_t)__half_as_ushort(hx) | ((uint32_t)__half_as_ushort(hy) << 16);
        uint32_t hi1 = (uint32_t)__half_as_ushort(hz) | ((uint32_t)__half_as_ushort(hw) << 16);
        uint32_t lo0 = pack_hi_f16x2(v.x - __half2float(hx), v.y - __half2float(hy));
        uint32_t lo1 = pack_hi_f16x2(v.z - __half2float(hz), v.w - __half2float(hw));
        ((uint2*)g_w16hi)[i] = make_uint2(hi0, hi1);
        ((uint2*)g_w16lo)[i] = make_uint2(lo0, lo1);
    }
}

// ---------------------------------------------------------------------------
// Kernel A: Wh = h @ W + bW via fp16 HMMA hi/lo split; B fragments pipelined
// one ntp group ahead; fused el/er + per-head er-max. (R14-proven)
// ---------------------------------------------------------------------------
#define ASTRIDE 72
#define WH_SMEM (128 * ASTRIDE * 2 * 2 + 64 * ASTRIDE * 2 * 2)

__global__ void __launch_bounds__(256) wh_mma_kernel(
    const float* __restrict__ bW, const float* __restrict__ a_l,
    const float* __restrict__ a_r, const float* __restrict__ bA)
{
    extern __shared__ __align__(16) unsigned short sm[];
    unsigned short* Ah = sm;
    unsigned short* Al = Ah + 128 * ASTRIDE;
    unsigned short* Bh = Al + 128 * ASTRIDE;
    unsigned short* Bl = Bh + 64 * ASTRIDE;
    __shared__ float redmax[8];

    const int t    = threadIdx.x;
    const int warp = t >> 5;
    const int lane = t & 31;
    const int i0   = blockIdx.x * 128;
    const int hh   = blockIdx.y;

    const uint32_t ahB = smem_u32(Ah), alB = smem_u32(Al);
    const uint32_t bhB = smem_u32(Bh), blB = smem_u32(Bl);

    float acc[8][4];
#pragma unroll
    for (int n = 0; n < 8; n++)
#pragma unroll
        for (int j = 0; j < 4; j++) acc[n][j] = 0.f;

    const uint32_t aRow = (uint32_t)(16 * warp + (lane & 15)) * (ASTRIDE * 2) + ((lane & 16) ? 16 : 0);
    const uint32_t bRow = (uint32_t)(lane & 15) * (ASTRIDE * 2) + ((lane & 16) ? 16 : 0);

    for (int ch = 0; ch < FIN / 64; ch++) {
        const int kc = ch * 64;
        __syncthreads();
#pragma unroll
        for (int it = 0; it < 4; it++) {
            int id = t + 256 * it;
            int r = id >> 3, c = id & 7;
            size_t src = (size_t)(i0 + r) * FIN + kc + c * 8;
            *(uint4*)&Ah[r * ASTRIDE + c * 8] = *(const uint4*)(g_h16hi + src);
            *(uint4*)&Al[r * ASTRIDE + c * 8] = *(const uint4*)(g_h16lo + src);
        }
#pragma unroll
        for (int it = 0; it < 2; it++) {
            int id = t + 256 * it;
            int r = id >> 3, c = id & 7;
            size_t src = ((size_t)hh * FIN + kc + r) * FO + c * 8;
            *(uint4*)&Bh[r * ASTRIDE + c * 8] = *(const uint4*)(g_w16hi + src);
            *(uint4*)&Bl[r * ASTRIDE + c * 8] = *(const uint4*)(g_w16lo + src);
        }
        __syncthreads();

#pragma unroll
        for (int kt = 0; kt < 4; kt++) {
            uint32_t ah0, ah1, ah2, ah3, al0, al1, al2, al3;
            LDSM4(ah0, ah1, ah2, ah3, ahB + aRow + kt * 32);
            LDSM4(al0, al1, al2, al3, alB + aRow + kt * 32);
            const uint32_t kOff = (uint32_t)(16 * kt) * (ASTRIDE * 2) + bRow;

            uint32_t bhc[4], blc[4], bhn[4], bln[4];
            LDSM4T(bhc[0], bhc[1], bhc[2], bhc[3], bhB + kOff);
            LDSM4T(blc[0], blc[1], blc[2], blc[3], blB + kOff);
#pragma unroll
            for (int ntp = 0; ntp < 4; ntp++) {
                if (ntp < 3) {
                    LDSM4T(bhn[0], bhn[1], bhn[2], bhn[3], bhB + kOff + 32 * (ntp + 1));
                    LDSM4T(bln[0], bln[1], bln[2], bln[3], blB + kOff + 32 * (ntp + 1));
                }
                MMA16816F16(acc[2 * ntp],     ah0, ah1, ah2, ah3, bhc[0], bhc[1]);
                MMA16816F16(acc[2 * ntp],     al0, al1, al2, al3, bhc[0], bhc[1]);
                MMA16816F16(acc[2 * ntp],     ah0, ah1, ah2, ah3, blc[0], blc[1]);
                MMA16816F16(acc[2 * ntp + 1], ah0, ah1, ah2, ah3, bhc[2], bhc[3]);
                MMA16816F16(acc[2 * ntp + 1], al0, al1, al2, al3, bhc[2], bhc[3]);
                MMA16816F16(acc[2 * ntp + 1], ah0, ah1, ah2, ah3, blc[2], blc[3]);
                if (ntp < 3) {
#pragma unroll
                    for (int z = 0; z < 4; z++) { bhc[z] = bhn[z]; blc[z] = bln[z]; }
                }
            }
        }
    }

    // ---- epilogue: bias, store fp16 Wh, fused el/er, er-max ----
    const int q  = lane >> 2;
    const int c2 = 2 * (lane & 3);
    const int r0 = i0 + 16 * warp + q;
    const int r1 = r0 + 8;

    float dl0 = 0.f, dr0 = 0.f, dl1 = 0.f, dr1 = 0.f;
#pragma unroll
    for (int nt = 0; nt < 8; nt++) {
        int col = 8 * nt + c2;
        float2 bw = *(const float2*)(bW + hh * FO + col);
        float2 al = *(const float2*)(a_l + hh * FO + col);
        float2 ar = *(const float2*)(a_r + hh * FO + col);
        float v00 = acc[nt][0] + bw.x, v01 = acc[nt][1] + bw.y;
        float v10 = acc[nt][2] + bw.x, v11 = acc[nt][3] + bw.y;
        *(uint32_t*)(g_wh16 + ((size_t)hh * NN + r0) * FO + col) = pack_hi_f16x2(v00, v01);
        *(uint32_t*)(g_wh16 + ((size_t)hh * NN + r1) * FO + col) = pack_hi_f16x2(v10, v11);
        dl0 += v00 * al.x + v01 * al.y;
        dr0 += v00 * ar.x + v01 * ar.y;
        dl1 += v10 * al.x + v11 * al.y;
        dr1 += v10 * ar.x + v11 * ar.y;
    }
#pragma unroll
    for (int off = 1; off < 4; off <<= 1) {
        dl0 += __shfl_xor_sync(0xffffffffu, dl0, off);
        dr0 += __shfl_xor_sync(0xffffffffu, dr0, off);
        dl1 += __shfl_xor_sync(0xffffffffu, dl1, off);
        dr1 += __shfl_xor_sync(0xffffffffu, dr1, off);
    }
    float er0s = dr0 * LOG2E, er1s = dr1 * LOG2E;
    if ((lane & 3) == 0) {
        float ba = bA[hh];
        g_el[hh * NN + r0] = (dl0 + ba) * LOG2E;
        g_er[hh * NN + r0] = er0s;
        g_el[hh * NN + r1] = (dl1 + ba) * LOG2E;
        g_er[hh * NN + r1] = er1s;
    }
    float wm = fmaxf(er0s, er1s);
#pragma unroll
    for (int off = 4; off < 32; off <<= 1)
        wm = fmaxf(wm, __shfl_xor_sync(0xffffffffu, wm, off));
    if (lane == 0) redmax[warp] = wm;
    __syncthreads();
    if (t == 0) {
        float m = redmax[0];
#pragma unroll
        for (int w = 1; w < 8; w++) m = fmaxf(m, redmax[w]);
        atomicMax(&g_ermax_enc[hh], f2ord(m));
    }
}

// ---------------------------------------------------------------------------
// Kernel C: fp16 HMMA flash-GAT, 128-wide j tiles; scores SW-pipelined one kt
// ahead; f16x2 fused score math. (R14-proven)
// ---------------------------------------------------------------------------
__device__ __forceinline__ float elu(float v) {
    return v > 0.f ? v : (__expf(v) - 1.f);
}

#define ALPHA2_F16 0x32663266u  /* (0.2, 0.2) fp16x2 */

__device__ __forceinline__ uint32_t pscore2(float elp, uint32_t d2, float2 er, uint32_t b2) {
    float x0 = elp + er.x;
    float x1 = elp + er.y;
    uint32_t xh, yh, mh, pe;
    asm("cvt.rn.f16x2.f32 %0, %1, %2;" : "=r"(xh) : "f"(x1), "f"(x0));
    asm("fma.rn.f16x2 %0, %1, %2, %3;" : "=r"(yh) : "r"(ALPHA2_F16), "r"(xh), "r"(d2));
    asm("max.f16x2 %0, %1, %2;" : "=r"(mh) : "r"(xh), "r"(yh));
    asm("ex2.approx.f16x2 %0, %1;" : "=r"(pe) : "r"(mh));
    uint32_t msk = ((b2 & 1u) ? 0x0000FFFFu : 0u) | ((b2 & 2u) ? 0xFFFF0000u : 0u);
    return pe & msk;
}

#define BSTRIDE 72
#define JT 128
#define ATTN_BS_BYTES (2 * JT * BSTRIDE * 2)            /* 36864 */
#define ATTN_SMEM (ATTN_BS_BYTES + 1024 + NN * 4)       /* 54272 */

__global__ void __launch_bounds__(256, 2) gat_attn_mma_kernel(float* __restrict__ out)
{
    extern __shared__ __align__(16) char dsm[];
    unsigned short* Bs = (unsigned short*)dsm;
    float2* els2 = (float2*)(dsm + ATTN_BS_BYTES);
    float* ers = (float*)(dsm + ATTN_BS_BYTES + 1024);

    const int t    = threadIdx.x;
    const int warp = t >> 5;
    const int lane = t & 31;
    const int i0   = blockIdx.x * 128;
    const int hh   = blockIdx.y;

    {
        const float4* src = (const float4*)(g_er + hh * NN);
#pragma unroll
        for (int it = 0; it < NN / 4 / 256; it++)
            ((float4*)ers)[t + 256 * it] = src[t + 256 * it];
    }

    if (t < 128) {
        float e = g_el[hh * NN + i0 + t];
        float z = e + ord2f(g_ermax_enc[hh]);
        float c = fmaxf(z, ALPHA * z);
        float d = (ALPHA - 1.f) * c;
        __half hd = __float2half_rn(d);
        uint32_t d2 = (uint32_t)__half_as_ushort(hd);
        d2 |= d2 << 16;
        els2[t] = make_float2(e - c, __uint_as_float(d2));
    }

    const int q  = lane >> 2;
    const int c2 = 2 * (lane & 3);
    const int rw0 = 16 * warp + q;

    const unsigned short* gwh = g_wh16 + (size_t)hh * NN * FO;
    const uint32_t* bitbase =
        g_bits + (size_t)(i0 + 16 * warp + (lane >> 1)) * NWORD + (lane & 1) * 2;

    const uint32_t bBase = smem_u32(Bs);
    const uint32_t lrowOff = (uint32_t)(lane & 15) * (BSTRIDE * 2) + ((lane & 16) ? 16 : 0);

    const int lk0 = t >> 3, lc0 = t & 7;
    const int lk1 = (t + 256) >> 3, lc1 = t & 7;

    float acc[8][4];
#pragma unroll
    for (int n = 0; n < 8; n++)
#pragma unroll
        for (int j = 0; j < 4; j++) acc[n][j] = 0.f;
    float accd[4] = {0.f, 0.f, 0.f, 0.f};
    const uint32_t ONES = 0x3C003C00u;

    {
#pragma unroll
        for (int hf = 0; hf < 2; hf++) {
            uint4 va = *(const uint4*)(gwh + (size_t)(hf * 64 + lk0) * FO + lc0 * 8);
            uint4 vb = *(const uint4*)(gwh + (size_t)(hf * 64 + lk1) * FO + lc1 * 8);
            *(uint4*)&Bs[(hf * 64 + lk0) * BSTRIDE + lc0 * 8] = va;
            *(uint4*)&Bs[(hf * 64 + lk1) * BSTRIDE + lc1 * 8] = vb;
        }
    }
    uint2 bvNext = *(const uint2*)(bitbase);
    __syncthreads();

    const float2 ec0 = els2[rw0];
    const float2 ec1 = els2[rw0 + 8];
    const float elp0 = ec0.x, elp1 = ec1.x;
    const uint32_t d20 = __float_as_uint(ec0.y), d21 = __float_as_uint(ec1.y);

    uint32_t w0[4], w1[4];
    auto distrib = [&](uint2 bv) {
        w0[0] = __shfl_sync(0xffffffffu, bv.x, 2 * q);
        w0[1] = __shfl_sync(0xffffffffu, bv.y, 2 * q);
        w0[2] = __shfl_sync(0xffffffffu, bv.x, 2 * q + 1);
        w0[3] = __shfl_sync(0xffffffffu, bv.y, 2 * q + 1);
        w1[0] = __shfl_sync(0xffffffffu, bv.x, 2 * q + 16);
        w1[1] = __shfl_sync(0xffffffffu, bv.y, 2 * q + 16);
        w1[2] = __shfl_sync(0xffffffffu, bv.x, 2 * q + 17);
        w1[3] = __shfl_sync(0xffffffffu, bv.y, 2 * q + 17);
    };

    auto scoreblk = [&](int jb0, int kt, uint32_t* a) {
        const int jb = jb0 + 16 * kt + c2;
        float2 e0 = *(const float2*)(ers + jb);
        float2 e1 = *(const float2*)(ers + jb + 8);
        const int wi = kt >> 1;
        const int sb = (kt & 1) * 16;
        uint32_t v0 = w0[wi] >> (sb + c2);
        uint32_t v1 = w1[wi] >> (sb + c2);
        a[0] = pscore2(elp0, d20, e0, v0 & 3u);
        a[1] = pscore2(elp1, d21, e0, v1 & 3u);
        a[2] = pscore2(elp0, d20, e1, (v0 >> 8) & 3u);
        a[3] = pscore2(elp1, d21, e1, (v1 >> 8) & 3u);
    };

    distrib(bvNext);
    uint32_t aF[4];
    scoreblk(0, 0, aF);

    for (int tile = 0; tile < NN / JT; tile++) {
        const int j0 = tile * JT;
        const int cur = tile & 1;
        const bool last = (tile == NN / JT - 1);

        if (!last) bvNext = *(const uint2*)(bitbase + (tile + 1) * 4);

        uint4 na, nb;
        if (!last) {
            const unsigned short* src = gwh + (size_t)(j0 + JT) * FO;
            na = *(const uint4*)(src + (size_t)lk0 * FO + lc0 * 8);
            nb = *(const uint4*)(src + (size_t)lk1 * FO + lc1 * 8);
        }

        const uint32_t bufOff = bBase + cur * (JT * BSTRIDE * 2) + lrowOff;
        unsigned short* dst = &Bs[(cur ^ 1) * JT * BSTRIDE];

#pragma unroll
        for (int kt = 0; kt < 8; kt++) {
            uint32_t aN[4];
            if (kt < 7)
                scoreblk(j0, kt + 1, aN);

            const uint32_t kOff = bufOff + (uint32_t)(16 * kt) * (BSTRIDE * 2);

            uint32_t bc[4], bn[4];
            LDSM4T(bc[0], bc[1], bc[2], bc[3], kOff);
#pragma unroll
            for (int ntp = 0; ntp < 4; ntp++) {
                if (ntp < 3)
                    LDSM4T(bn[0], bn[1], bn[2], bn[3], kOff + 32 * (ntp + 1));
                MMA16816F16(acc[2 * ntp],     aF[0], aF[1], aF[2], aF[3], bc[0], bc[1]);
                MMA16816F16(acc[2 * ntp + 1], aF[0], aF[1], aF[2], aF[3], bc[2], bc[3]);
                if (ntp < 3) {
#pragma unroll
                    for (int z = 0; z < 4; z++) bc[z] = bn[z];
                }
            }
            MMA16816F16(accd, aF[0], aF[1], aF[2], aF[3], ONES, ONES);

            if (kt == 3 && !last) {
                *(uint4*)&dst[lk0 * BSTRIDE + lc0 * 8] = na;
                *(uint4*)&dst[lk1 * BSTRIDE + lc1 * 8] = nb;
                const unsigned short* src = gwh + (size_t)(j0 + JT + 64) * FO;
                na = *(const uint4*)(src + (size_t)lk0 * FO + lc0 * 8);
                nb = *(const uint4*)(src + (size_t)lk1 * FO + lc1 * 8);
            }

            if (kt < 7) {
                aF[0] = aN[0]; aF[1] = aN[1]; aF[2] = aN[2]; aF[3] = aN[3];
            }
        }

        if (!last) {
            *(uint4*)&dst[(64 + lk0) * BSTRIDE + lc0 * 8] = na;
            *(uint4*)&dst[(64 + lk1) * BSTRIDE + lc1 * 8] = nb;
            distrib(bvNext);
            scoreblk(j0 + JT, 0, aF);
        }
        __syncthreads();
    }

    const float inv0 = 1.f / accd[0];
    const float inv1 = 1.f / accd[2];

    float* ob0 = out + (size_t)(i0 + rw0) * OUTW + hh * FO + c2;
    float* ob1 = ob0 + (size_t)8 * OUTW;
#pragma unroll
    for (int nt = 0; nt < 8; nt++) {
        float2 v0 = make_float2(elu(acc[nt][0] * inv0), elu(acc[nt][1] * inv0));
        float2 v1 = make_float2(elu(acc[nt][2] * inv1), elu(acc[nt][3] * inv1));
        *(float2*)(ob0 + 8 * nt) = v0;
        *(float2*)(ob1 + 8 * nt) = v1;
    }
}

// ---------------------------------------------------------------------------
extern "C" void kernel_launch(void* const* d_in, const int* in_sizes, int n_in,
                              void* d_out, int out_size)
{
    const float* h    = (const float*)d_in[0];  // [N, FIN]
    const int*   mask = (const int*)  d_in[1];  // [N, N]
    const float* W    = (const float*)d_in[2];  // [H, FIN, FO]
    const float* bW   = (const float*)d_in[3];  // [H, FO]
    const float* a_l  = (const float*)d_in[4];  // [H, FO]
    const float* a_r  = (const float*)d_in[5];  // [H, FO]
    const float* bA   = (const float*)d_in[6];  // [H]
    float* out = (float*)d_out;                 // [N, H*FO]

    cudaFuncSetAttribute(wh_mma_kernel,
                         cudaFuncAttributeMaxDynamicSharedMemorySize, WH_SMEM);
    cudaFuncSetAttribute(gat_attn_mma_kernel,
                         cudaFuncAttributeMaxDynamicSharedMemorySize, ATTN_SMEM);

    prep_kernel<<<2048, 256>>>(h, W, mask);
    wh_mma_kernel<<<dim3(NN / 128, NH), 256, WH_SMEM>>>(bW, a_l, a_r, bA);
    gat_attn_mma_kernel<<<dim3(NN / 128, NH), 256, ATTN_SMEM>>>(out);
}

// round 17
// speedup vs baseline: 1.1784x; 1.0523x over previous
#include <cuda_runtime.h>
#include <cuda_fp16.h>
#include <cstdint>

#define NN 4096
#define FIN 512
#define FO 64
#define NH 8
#define ALPHA 0.2f
#define OUTW (NH * FO)  /* 512 */
#define LOG2E 1.4426950408889634f
#define NWORD (NN / 32)  /* 128 */

// ---------------------------------------------------------------------------
// Scratch (static device globals)
// ---------------------------------------------------------------------------
__device__ unsigned short g_h16hi[NN * FIN];     // fp16 of h, [n][k]
__device__ unsigned short g_w16hi[NH * FIN * FO];// fp16 hi of W, [h][k][n]
__device__ unsigned short g_w16lo[NH * FIN * FO];// fp16 lo of W
__device__ unsigned short g_wh16[NH * NN * FO];  // fp16 Wh, [h][n][o]
__device__ float g_el[NH * NN];                  // el * log2e (incl bA)
__device__ float g_er[NH * NN];                  // er * log2e
__device__ unsigned int g_ermax_enc[NH];         // order-preserving encoded max
__device__ uint32_t g_bits[NN * NWORD];          // mask bitmap [i][j/32]

__device__ __forceinline__ uint32_t smem_u32(const void* p) {
    uint32_t a;
    asm("{ .reg .u64 t; cvta.to.shared.u64 t, %1; cvt.u32.u64 %0, t; }" : "=r"(a) : "l"(p));
    return a;
}

__device__ __forceinline__ unsigned int f2ord(float f) {
    unsigned int u = __float_as_uint(f);
    return (u & 0x80000000u) ? ~u : (u | 0x80000000u);
}
__device__ __forceinline__ float ord2f(unsigned int k) {
    unsigned int u = (k & 0x80000000u) ? (k & 0x7FFFFFFFu) : ~k;
    return __uint_as_float(u);
}

#define MMA16816F16(acc, a0, a1, a2, a3, b0, b1) \
    asm volatile("mma.sync.aligned.m16n8k16.row.col.f32.f16.f16.f32 " \
        "{%0,%1,%2,%3}, {%4,%5,%6,%7}, {%8,%9}, {%0,%1,%2,%3};" \
        : "+f"((acc)[0]), "+f"((acc)[1]), "+f"((acc)[2]), "+f"((acc)[3]) \
        : "r"(a0), "r"(a1), "r"(a2), "r"(a3), "r"(b0), "r"(b1))

#define LDSM4T(r0, r1, r2, r3, a) \
    asm volatile("ldmatrix.sync.aligned.m8n8.x4.trans.shared.b16 {%0,%1,%2,%3}, [%4];" \
        : "=r"(r0), "=r"(r1), "=r"(r2), "=r"(r3) : "r"(a))

#define LDSM4(r0, r1, r2, r3, a) \
    asm volatile("ldmatrix.sync.aligned.m8n8.x4.shared.b16 {%0,%1,%2,%3}, [%4];" \
        : "=r"(r0), "=r"(r1), "=r"(r2), "=r"(r3) : "r"(a))

__device__ __forceinline__ uint32_t pack_hi_f16x2(float a, float b) {
    uint32_t r;
    asm("cvt.rn.f16x2.f32 %0, %1, %2;" : "=r"(r) : "f"(b), "f"(a));
    return r;
}

// ---------------------------------------------------------------------------
// Kernel P: mask -> bitmap (MLP-16); h -> fp16; W -> fp16 hi/lo; init ermax.
// ---------------------------------------------------------------------------
__global__ void __launch_bounds__(256) prep_kernel(
    const float* __restrict__ h, const float* __restrict__ W,
    const int* __restrict__ mask)
{
    if (blockIdx.x == 0 && threadIdx.x < NH)
        g_ermax_enc[threadIdx.x] = 0u;  // below every encoded float

    const int stride = gridDim.x * 256;

    // mask -> bits first: 16 words per warp-iteration (MLP=16)
    {
        const int wid_g = (blockIdx.x * 256 + threadIdx.x) >> 5;
        const int lane  = threadIdx.x & 31;
        const int nwarp = stride >> 5;
        for (int g = wid_g; g < NN * NWORD / 16; g += nwarp) {
            int w0  = 16 * g;
            int row = w0 >> 7;
            int wd  = w0 & (NWORD - 1);
            const int* base = mask + (size_t)row * NN + wd * 32 + lane;
            int m[16];
#pragma unroll
            for (int k = 0; k < 16; k++) m[k] = base[32 * k];
            uint32_t b[16];
#pragma unroll
            for (int k = 0; k < 16; k++) b[k] = __ballot_sync(0xffffffffu, m[k] > 0);
            if (lane == 0) {
#pragma unroll
                for (int s = 0; s < 4; s++)
                    *(uint4*)(g_bits + w0 + 4 * s) =
                        make_uint4(b[4 * s], b[4 * s + 1], b[4 * s + 2], b[4 * s + 3]);
            }
        }
    }

    // h -> fp16 (single precision level; h-lo correction dropped)
    for (int i = blockIdx.x * 256 + threadIdx.x; i < NN * FIN / 4; i += stride) {
        float4 v = ((const float4*)h)[i];
        uint32_t hi0 = pack_hi_f16x2(v.x, v.y);
        uint32_t hi1 = pack_hi_f16x2(v.z, v.w);
        ((uint2*)g_h16hi)[i] = make_uint2(hi0, hi1);
    }
    // W -> fp16 hi/lo
    for (int i = blockIdx.x * 256 + threadIdx.x; i < NH * FIN * FO / 4; i += stride) {
        float4 v = ((const float4*)W)[i];
        __half hx = __float2half_rn(v.x), hy = __float2half_rn(v.y);
        __half hz = __float2half_rn(v.z), hw = __float2half_rn(v.w);
        uint32_t hi0 = (uint32_t)__half_as_ushort(hx) | ((uint32_t)__half_as_ushort(hy) << 16);
        uint32_t hi1 = (uint32_t)__half_as_ushort(hz) | ((uint32_t)__half_as_ushort(hw) << 16);
        uint32_t lo0 = pack_hi_f16x2(v.x - __half2float(hx), v.y - __half2float(hy));
        uint32_t lo1 = pack_hi_f16x2(v.z - __half2float(hz), v.w - __half2float(hw));
        ((uint2*)g_w16hi)[i] = make_uint2(hi0, hi1);
        ((uint2*)g_w16lo)[i] = make_uint2(lo0, lo1);
    }
}

// ---------------------------------------------------------------------------
// Kernel A: Wh = h16 @ (W_hi + W_lo) + bW (2 MMAs/step); B fragments pipelined;
// fused el/er + per-head er-max.
// ---------------------------------------------------------------------------
#define ASTRIDE 72
#define WH_SMEM (128 * ASTRIDE * 2 + 64 * ASTRIDE * 2 * 2)  /* Ah + Bh + Bl = 36864 */

__global__ void __launch_bounds__(256) wh_mma_kernel(
    const float* __restrict__ bW, const float* __restrict__ a_l,
    const float* __restrict__ a_r, const float* __restrict__ bA)
{
    extern __shared__ __align__(16) unsigned short sm[];
    unsigned short* Ah = sm;                     // 128 x ASTRIDE
    unsigned short* Bh = Ah + 128 * ASTRIDE;     // 64 x ASTRIDE
    unsigned short* Bl = Bh + 64 * ASTRIDE;
    __shared__ float redmax[8];

    const int t    = threadIdx.x;
    const int warp = t >> 5;
    const int lane = t & 31;
    const int i0   = blockIdx.x * 128;
    const int hh   = blockIdx.y;

    const uint32_t ahB = smem_u32(Ah);
    const uint32_t bhB = smem_u32(Bh), blB = smem_u32(Bl);

    float acc[8][4];
#pragma unroll
    for (int n = 0; n < 8; n++)
#pragma unroll
        for (int j = 0; j < 4; j++) acc[n][j] = 0.f;

    const uint32_t aRow = (uint32_t)(16 * warp + (lane & 15)) * (ASTRIDE * 2) + ((lane & 16) ? 16 : 0);
    const uint32_t bRow = (uint32_t)(lane & 15) * (ASTRIDE * 2) + ((lane & 16) ? 16 : 0);

    for (int ch = 0; ch < FIN / 64; ch++) {
        const int kc = ch * 64;
        __syncthreads();
#pragma unroll
        for (int it = 0; it < 4; it++) {
            int id = t + 256 * it;
            int r = id >> 3, c = id & 7;
            size_t src = (size_t)(i0 + r) * FIN + kc + c * 8;
            *(uint4*)&Ah[r * ASTRIDE + c * 8] = *(const uint4*)(g_h16hi + src);
        }
#pragma unroll
        for (int it = 0; it < 2; it++) {
            int id = t + 256 * it;
            int r = id >> 3, c = id & 7;
            size_t src = ((size_t)hh * FIN + kc + r) * FO + c * 8;
            *(uint4*)&Bh[r * ASTRIDE + c * 8] = *(const uint4*)(g_w16hi + src);
            *(uint4*)&Bl[r * ASTRIDE + c * 8] = *(const uint4*)(g_w16lo + src);
        }
        __syncthreads();

#pragma unroll
        for (int kt = 0; kt < 4; kt++) {
            uint32_t ah0, ah1, ah2, ah3;
            LDSM4(ah0, ah1, ah2, ah3, ahB + aRow + kt * 32);
            const uint32_t kOff = (uint32_t)(16 * kt) * (ASTRIDE * 2) + bRow;

            uint32_t bhc[4], blc[4], bhn[4], bln[4];
            LDSM4T(bhc[0], bhc[1], bhc[2], bhc[3], bhB + kOff);
            LDSM4T(blc[0], blc[1], blc[2], blc[3], blB + kOff);
#pragma unroll
            for (int ntp = 0; ntp < 4; ntp++) {
                if (ntp < 3) {
                    LDSM4T(bhn[0], bhn[1], bhn[2], bhn[3], bhB + kOff + 32 * (ntp + 1));
                    LDSM4T(bln[0], bln[1], bln[2], bln[3], blB + kOff + 32 * (ntp + 1));
                }
                MMA16816F16(acc[2 * ntp],     ah0, ah1, ah2, ah3, bhc[0], bhc[1]);
                MMA16816F16(acc[2 * ntp],     ah0, ah1, ah2, ah3, blc[0], blc[1]);
                MMA16816F16(acc[2 * ntp + 1], ah0, ah1, ah2, ah3, bhc[2], bhc[3]);
                MMA16816F16(acc[2 * ntp + 1], ah0, ah1, ah2, ah3, blc[2], blc[3]);
                if (ntp < 3) {
#pragma unroll
                    for (int z = 0; z < 4; z++) { bhc[z] = bhn[z]; blc[z] = bln[z]; }
                }
            }
        }
    }

    // ---- epilogue: bias, store fp16 Wh, fused el/er, er-max ----
    const int q  = lane >> 2;
    const int c2 = 2 * (lane & 3);
    const int r0 = i0 + 16 * warp + q;
    const int r1 = r0 + 8;

    float dl0 = 0.f, dr0 = 0.f, dl1 = 0.f, dr1 = 0.f;
#pragma unroll
    for (int nt = 0; nt < 8; nt++) {
        int col = 8 * nt + c2;
        float2 bw = *(const float2*)(bW + hh * FO + col);
        float2 al = *(const float2*)(a_l + hh * FO + col);
        float2 ar = *(const float2*)(a_r + hh * FO + col);
        float v00 = acc[nt][0] + bw.x, v01 = acc[nt][1] + bw.y;
        float v10 = acc[nt][2] + bw.x, v11 = acc[nt][3] + bw.y;
        *(uint32_t*)(g_wh16 + ((size_t)hh * NN + r0) * FO + col) = pack_hi_f16x2(v00, v01);
        *(uint32_t*)(g_wh16 + ((size_t)hh * NN + r1) * FO + col) = pack_hi_f16x2(v10, v11);
        dl0 += v00 * al.x + v01 * al.y;
        dr0 += v00 * ar.x + v01 * ar.y;
        dl1 += v10 * al.x + v11 * al.y;
        dr1 += v10 * ar.x + v11 * ar.y;
    }
#pragma unroll
    for (int off = 1; off < 4; off <<= 1) {
        dl0 += __shfl_xor_sync(0xffffffffu, dl0, off);
        dr0 += __shfl_xor_sync(0xffffffffu, dr0, off);
        dl1 += __shfl_xor_sync(0xffffffffu, dl1, off);
        dr1 += __shfl_xor_sync(0xffffffffu, dr1, off);
    }
    float er0s = dr0 * LOG2E, er1s = dr1 * LOG2E;
    if ((lane & 3) == 0) {
        float ba = bA[hh];
        g_el[hh * NN + r0] = (dl0 + ba) * LOG2E;
        g_er[hh * NN + r0] = er0s;
        g_el[hh * NN + r1] = (dl1 + ba) * LOG2E;
        g_er[hh * NN + r1] = er1s;
    }
    float wm = fmaxf(er0s, er1s);
#pragma unroll
    for (int off = 4; off < 32; off <<= 1)
        wm = fmaxf(wm, __shfl_xor_sync(0xffffffffu, wm, off));
    if (lane == 0) redmax[warp] = wm;
    __syncthreads();
    if (t == 0) {
        float m = redmax[0];
#pragma unroll
        for (int w = 1; w < 8; w++) m = fmaxf(m, redmax[w]);
        atomicMax(&g_ermax_enc[hh], f2ord(m));
    }
}

// ---------------------------------------------------------------------------
// Kernel C: fp16 HMMA flash-GAT, 128-wide j tiles; scores SW-pipelined one kt
// ahead; f16x2 fused score math. (R14-proven, unchanged)
// ---------------------------------------------------------------------------
__device__ __forceinline__ float elu(float v) {
    return v > 0.f ? v : (__expf(v) - 1.f);
}

#define ALPHA2_F16 0x32663266u  /* (0.2, 0.2) fp16x2 */

__device__ __forceinline__ uint32_t pscore2(float elp, uint32_t d2, float2 er, uint32_t b2) {
    float x0 = elp + er.x;
    float x1 = elp + er.y;
    uint32_t xh, yh, mh, pe;
    asm("cvt.rn.f16x2.f32 %0, %1, %2;" : "=r"(xh) : "f"(x1), "f"(x0));
    asm("fma.rn.f16x2 %0, %1, %2, %3;" : "=r"(yh) : "r"(ALPHA2_F16), "r"(xh), "r"(d2));
    asm("max.f16x2 %0, %1, %2;" : "=r"(mh) : "r"(xh), "r"(yh));
    asm("ex2.approx.f16x2 %0, %1;" : "=r"(pe) : "r"(mh));
    uint32_t msk = ((b2 & 1u) ? 0x0000FFFFu : 0u) | ((b2 & 2u) ? 0xFFFF0000u : 0u);
    return pe & msk;
}

#define BSTRIDE 72
#define JT 128
#define ATTN_BS_BYTES (2 * JT * BSTRIDE * 2)            /* 36864 */
#define ATTN_SMEM (ATTN_BS_BYTES + 1024 + NN * 4)       /* 54272 */

__global__ void __launch_bounds__(256, 2) gat_attn_mma_kernel(float* __restrict__ out)
{
    extern __shared__ __align__(16) char dsm[];
    unsigned short* Bs = (unsigned short*)dsm;
    float2* els2 = (float2*)(dsm + ATTN_BS_BYTES);
    float* ers = (float*)(dsm + ATTN_BS_BYTES + 1024);

    const int t    = threadIdx.x;
    const int warp = t >> 5;
    const int lane = t & 31;
    const int i0   = blockIdx.x * 128;
    const int hh   = blockIdx.y;

    {
        const float4* src = (const float4*)(g_er + hh * NN);
#pragma unroll
        for (int it = 0; it < NN / 4 / 256; it++)
            ((float4*)ers)[t + 256 * it] = src[t + 256 * it];
    }

    if (t < 128) {
        float e = g_el[hh * NN + i0 + t];
        float z = e + ord2f(g_ermax_enc[hh]);
        float c = fmaxf(z, ALPHA * z);
        float d = (ALPHA - 1.f) * c;
        __half hd = __float2half_rn(d);
        uint32_t d2 = (uint32_t)__half_as_ushort(hd);
        d2 |= d2 << 16;
        els2[t] = make_float2(e - c, __uint_as_float(d2));
    }

    const int q  = lane >> 2;
    const int c2 = 2 * (lane & 3);
    const int rw0 = 16 * warp + q;

    const unsigned short* gwh = g_wh16 + (size_t)hh * NN * FO;
    const uint32_t* bitbase =
        g_bits + (size_t)(i0 + 16 * warp + (lane >> 1)) * NWORD + (lane & 1) * 2;

    const uint32_t bBase = smem_u32(Bs);
    const uint32_t lrowOff = (uint32_t)(lane & 15) * (BSTRIDE * 2) + ((lane & 16) ? 16 : 0);

    const int lk0 = t >> 3, lc0 = t & 7;
    const int lk1 = (t + 256) >> 3, lc1 = t & 7;

    float acc[8][4];
#pragma unroll
    for (int n = 0; n < 8; n++)
#pragma unroll
        for (int j = 0; j < 4; j++) acc[n][j] = 0.f;
    float accd[4] = {0.f, 0.f, 0.f, 0.f};
    const uint32_t ONES = 0x3C003C00u;

    {
#pragma unroll
        for (int hf = 0; hf < 2; hf++) {
            uint4 va = *(const uint4*)(gwh + (size_t)(hf * 64 + lk0) * FO + lc0 * 8);
            uint4 vb = *(const uint4*)(gwh + (size_t)(hf * 64 + lk1) * FO + lc1 * 8);
            *(uint4*)&Bs[(hf * 64 + lk0) * BSTRIDE + lc0 * 8] = va;
            *(uint4*)&Bs[(hf * 64 + lk1) * BSTRIDE + lc1 * 8] = vb;
        }
    }
    uint2 bvNext = *(const uint2*)(bitbase);
    __syncthreads();

    const float2 ec0 = els2[rw0];
    const float2 ec1 = els2[rw0 + 8];
    const float elp0 = ec0.x, elp1 = ec1.x;
    const uint32_t d20 = __float_as_uint(ec0.y), d21 = __float_as_uint(ec1.y);

    uint32_t w0[4], w1[4];
    auto distrib = [&](uint2 bv) {
        w0[0] = __shfl_sync(0xffffffffu, bv.x, 2 * q);
        w0[1] = __shfl_sync(0xffffffffu, bv.y, 2 * q);
        w0[2] = __shfl_sync(0xffffffffu, bv.x, 2 * q + 1);
        w0[3] = __shfl_sync(0xffffffffu, bv.y, 2 * q + 1);
        w1[0] = __shfl_sync(0xffffffffu, bv.x, 2 * q + 16);
        w1[1] = __shfl_sync(0xffffffffu, bv.y, 2 * q + 16);
        w1[2] = __shfl_sync(0xffffffffu, bv.x, 2 * q + 17);
        w1[3] = __shfl_sync(0xffffffffu, bv.y, 2 * q + 17);
    };

    auto scoreblk = [&](int jb0, int kt, uint32_t* a) {
        const int jb = jb0 + 16 * kt + c2;
        float2 e0 = *(const float2*)(ers + jb);
        float2 e1 = *(const float2*)(ers + jb + 8);
        const int wi = kt >> 1;
        const int sb = (kt & 1) * 16;
        uint32_t v0 = w0[wi] >> (sb + c2);
        uint32_t v1 = w1[wi] >> (sb + c2);
        a[0] = pscore2(elp0, d20, e0, v0 & 3u);
        a[1] = pscore2(elp1, d21, e0, v1 & 3u);
        a[2] = pscore2(elp0, d20, e1, (v0 >> 8) & 3u);
        a[3] = pscore2(elp1, d21, e1, (v1 >> 8) & 3u);
    };

    distrib(bvNext);
    uint32_t aF[4];
    scoreblk(0, 0, aF);

    for (int tile = 0; tile < NN / JT; tile++) {
        const int j0 = tile * JT;
        const int cur = tile & 1;
        const bool last = (tile == NN / JT - 1);

        if (!last) bvNext = *(const uint2*)(bitbase + (tile + 1) * 4);

        uint4 na, nb;
        if (!last) {
            const unsigned short* src = gwh + (size_t)(j0 + JT) * FO;
            na = *(const uint4*)(src + (size_t)lk0 * FO + lc0 * 8);
            nb = *(const uint4*)(src + (size_t)lk1 * FO + lc1 * 8);
        }

        const uint32_t bufOff = bBase + cur * (JT * BSTRIDE * 2) + lrowOff;
        unsigned short* dst = &Bs[(cur ^ 1) * JT * BSTRIDE];

#pragma unroll
        for (int kt = 0; kt < 8; kt++) {
            uint32_t aN[4];
            if (kt < 7)
                scoreblk(j0, kt + 1, aN);

            const uint32_t kOff = bufOff + (uint32_t)(16 * kt) * (BSTRIDE * 2);

            uint32_t bc[4], bn[4];
            LDSM4T(bc[0], bc[1], bc[2], bc[3], kOff);
#pragma unroll
            for (int ntp = 0; ntp < 4; ntp++) {
                if (ntp < 3)
                    LDSM4T(bn[0], bn[1], bn[2], bn[3], kOff + 32 * (ntp + 1));
                MMA16816F16(acc[2 * ntp],     aF[0], aF[1], aF[2], aF[3], bc[0], bc[1]);
                MMA16816F16(acc[2 * ntp + 1], aF[0], aF[1], aF[2], aF[3], bc[2], bc[3]);
                if (ntp < 3) {
#pragma unroll
                    for (int z = 0; z < 4; z++) bc[z] = bn[z];
                }
            }
            MMA16816F16(accd, aF[0], aF[1], aF[2], aF[3], ONES, ONES);

            if (kt == 3 && !last) {
                *(uint4*)&dst[lk0 * BSTRIDE + lc0 * 8] = na;
                *(uint4*)&dst[lk1 * BSTRIDE + lc1 * 8] = nb;
                const unsigned short* src = gwh + (size_t)(j0 + JT + 64) * FO;
                na = *(const uint4*)(src + (size_t)lk0 * FO + lc0 * 8);
                nb = *(const uint4*)(src + (size_t)lk1 * FO + lc1 * 8);
            }

            if (kt < 7) {
                aF[0] = aN[0]; aF[1] = aN[1]; aF[2] = aN[2]; aF[3] = aN[3];
            }
        }

        if (!last) {
            *(uint4*)&dst[(64 + lk0) * BSTRIDE + lc0 * 8] = na;
            *(uint4*)&dst[(64 + lk1) * BSTRIDE + lc1 * 8] = nb;
            distrib(bvNext);
            scoreblk(j0 + JT, 0, aF);
        }
        __syncthreads();
    }

    const float inv0 = 1.f / accd[0];
    const float inv1 = 1.f / accd[2];

    float* ob0 = out + (size_t)(i0 + rw0) * OUTW + hh * FO + c2;
    float* ob1 = ob0 + (size_t)8 * OUTW;
#pragma unroll
    for (int nt = 0; nt < 8; nt++) {
        float2 v0 = make_float2(elu(acc[nt][0] * inv0), elu(acc[nt][1] * inv0));
        float2 v1 = make_float2(elu(acc[nt][2] * inv1), elu(acc[nt][3] * inv1));
        *(float2*)(ob0 + 8 * nt) = v0;
        *(float2*)(ob1 + 8 * nt) = v1;
    }
}

// ---------------------------------------------------------------------------
extern "C" void kernel_launch(void* const* d_in, const int* in_sizes, int n_in,
                              void* d_out, int out_size)
{
    const float* h    = (const float*)d_in[0];  // [N, FIN]
    const int*   mask = (const int*)  d_in[1];  // [N, N]
    const float* W    = (const float*)d_in[2];  // [H, FIN, FO]
    const float* bW   = (const float*)d_in[3];  // [H, FO]
    const float* a_l  = (const float*)d_in[4];  // [H, FO]
    const float* a_r  = (const float*)d_in[5];  // [H, FO]
    const float* bA   = (const float*)d_in[6];  // [H]
    float* out = (float*)d_out;                 // [N, H*FO]

    cudaFuncSetAttribute(wh_mma_kernel,
                         cudaFuncAttributeMaxDynamicSharedMemorySize, WH_SMEM);
    cudaFuncSetAttribute(gat_attn_mma_kernel,
                         cudaFuncAttributeMaxDynamicSharedMemorySize, ATTN_SMEM);

    prep_kernel<<<2048, 256>>>(h, W, mask);
    wh_mma_kernel<<<dim3(NN / 128, NH), 256, WH_SMEM>>>(bW, a_l, a_r, bA);
    gat_attn_mma_kernel<<<dim3(NN / 128, NH), 256, ATTN_SMEM>>>(out);
}